// round 8
// baseline (speedup 1.0000x reference)
#include <cuda_runtime.h>

// SinusoidalEmbedding: out[b][s][d] = emb_table[x[b][s]][d] + PE[s][d]
// PE[s][2i] = sin(s*f_i), PE[s][2i+1] = cos(s*f_i), f_i = 10000^(-2i/1024)
//
// R6: R2 layout reshaped to 256-bit accesses — 128 threads/CTA, one CTA per
// position, each thread owns 8 consecutive floats (32B). Gathers use
// ld.global.nc.L2::evict_last.v8.b32 (sm_103a only allows evict_last at
// 256-bit width): dup-row gathers stay resident in L2 against the 128MB
// write stream, and LDG/STG instruction count halves.

#define BQ      8
#define S_LEN   4096
#define D_M     1024
#define TPB     128      // threads per CTA; each owns 8 floats -> 128*8 = 1024

__device__ __forceinline__ void ldg_el_v8(const float* p, float* v) {
    unsigned r0, r1, r2, r3, r4, r5, r6, r7;
    asm volatile("ld.global.nc.L2::evict_last.v8.b32 {%0,%1,%2,%3,%4,%5,%6,%7}, [%8];"
                 : "=r"(r0), "=r"(r1), "=r"(r2), "=r"(r3),
                   "=r"(r4), "=r"(r5), "=r"(r6), "=r"(r7)
                 : "l"(p));
    v[0] = __uint_as_float(r0); v[1] = __uint_as_float(r1);
    v[2] = __uint_as_float(r2); v[3] = __uint_as_float(r3);
    v[4] = __uint_as_float(r4); v[5] = __uint_as_float(r5);
    v[6] = __uint_as_float(r6); v[7] = __uint_as_float(r7);
}

__global__ __launch_bounds__(TPB)
void sinemb_kernel(const void* __restrict__ xraw,
                   const float* __restrict__ emb,
                   float* __restrict__ out)
{
    const int t = threadIdx.x;          // owns floats d = 8t .. 8t+7
    const int s = blockIdx.x;           // position

    // ---- index dtype detect (int64 vs int32), uniform broadcast loads ----
    const unsigned int* w = (const unsigned int*)xraw;
    const bool is64 = ((w[1] | w[3] | w[5] | w[7]) == 0u);

    // ---- gather rows for this position across the batch (uniform per CTA) ----
    int rows[BQ];
    if (is64) {
        const long long* x64 = (const long long*)xraw;
        #pragma unroll
        for (int b = 0; b < BQ; b++) rows[b] = (int)x64[(long long)b * S_LEN + s];
    } else {
        const int* x32 = (const int*)xraw;
        #pragma unroll
        for (int b = 0; b < BQ; b++) rows[b] = x32[b * S_LEN + s];
    }

    // ---- positional encoding: 4 (sin,cos) pairs for this thread's 8 floats ----
    // pair i of this thread corresponds to frequency index 4t+i.
    // f_i = 2^(c_exp * i), c_exp = -2*log2(10000)/1024
    const float c_exp = -0.02595256324130752f;
    const float fs = (float)s;
    float p[8];
    #pragma unroll
    for (int i = 0; i < 4; i++) {
        float f = exp2f(c_exp * (float)(4 * t + i));
        sincosf(fs * f, &p[2 * i], &p[2 * i + 1]);
    }

    // ---- 8 gather (256-bit, evict_last) + add + store ----
    float4* out4 = (float4*)out;
    #pragma unroll
    for (int b = 0; b < BQ; b++) {
        float e[8];
        ldg_el_v8(emb + (long long)rows[b] * D_M + 8 * t, e);
        float4 o0, o1;
        o0.x = e[0] + p[0]; o0.y = e[1] + p[1];
        o0.z = e[2] + p[2]; o0.w = e[3] + p[3];
        o1.x = e[4] + p[4]; o1.y = e[5] + p[5];
        o1.z = e[6] + p[6]; o1.w = e[7] + p[7];
        long long o_base = ((long long)b * S_LEN + s) * (D_M / 4) + 2 * t;
        out4[o_base]     = o0;
        out4[o_base + 1] = o1;
    }
}

extern "C" void kernel_launch(void* const* d_in, const int* in_sizes, int n_in,
                              void* d_out, int out_size)
{
    const void*  x   = d_in[0];                 // [8, 4096] int64 (or int32)
    const float* emb = (const float*)d_in[1];   // [50257, 1024] fp32
    float*       out = (float*)d_out;           // [8, 4096, 1024] fp32

    sinemb_kernel<<<S_LEN, TPB>>>(x, emb, out);
}

// round 10
// speedup vs baseline: 1.0817x; 1.0817x over previous
#include <cuda_runtime.h>

// SinusoidalEmbedding: out[b][s][d] = emb_table[x[b][s]][d] + PE[s][d]
// PE[s][2i] = sin(s*f_i), PE[s][2i+1] = cos(s*f_i), f_i = 10000^(-2i/1024)
//
// R7 resubmit (previous round was an infra failure, kernel never ran):
// isolate the 256-bit access shape from R6's evict_last hint (hints have
// regressed twice: R3 .cs, R6 evict_last -> default L2 policy only).
// 256 threads/CTA covering TWO positions: thread t -> position 2*blk + t/128,
// floats 8*(t%128)..+7. Plain ld.global.nc.v8 / st.global.v8: half the
// LDG/STG instructions and L1tex wavefronts of R2, same coalescing, index
// loads amortized over 2 positions. No cache hints, natural occupancy.

#define BQ      8
#define S_LEN   4096
#define D_M     1024
#define TPB     256
#define POS_PER_CTA 2

__device__ __forceinline__ void ldg_v8(const float* p, float* v) {
    unsigned r0, r1, r2, r3, r4, r5, r6, r7;
    asm volatile("ld.global.nc.v8.b32 {%0,%1,%2,%3,%4,%5,%6,%7}, [%8];"
                 : "=r"(r0), "=r"(r1), "=r"(r2), "=r"(r3),
                   "=r"(r4), "=r"(r5), "=r"(r6), "=r"(r7)
                 : "l"(p));
    v[0] = __uint_as_float(r0); v[1] = __uint_as_float(r1);
    v[2] = __uint_as_float(r2); v[3] = __uint_as_float(r3);
    v[4] = __uint_as_float(r4); v[5] = __uint_as_float(r5);
    v[6] = __uint_as_float(r6); v[7] = __uint_as_float(r7);
}

__device__ __forceinline__ void stg_v8(float* p, const float* v) {
    asm volatile("st.global.v8.b32 [%0], {%1,%2,%3,%4,%5,%6,%7,%8};"
                 :: "l"(p),
                    "r"(__float_as_uint(v[0])), "r"(__float_as_uint(v[1])),
                    "r"(__float_as_uint(v[2])), "r"(__float_as_uint(v[3])),
                    "r"(__float_as_uint(v[4])), "r"(__float_as_uint(v[5])),
                    "r"(__float_as_uint(v[6])), "r"(__float_as_uint(v[7]))
                 : "memory");
}

__global__ __launch_bounds__(TPB)
void sinemb_kernel(const void* __restrict__ xraw,
                   const float* __restrict__ emb,
                   float* __restrict__ out)
{
    const int t    = threadIdx.x;
    const int lane = t & 127;                        // owns floats 8*lane..+7
    const int s    = blockIdx.x * POS_PER_CTA + (t >> 7);  // position

    // ---- index dtype detect (int64 vs int32) ----
    const unsigned int* w = (const unsigned int*)xraw;
    const bool is64 = ((w[1] | w[3] | w[5] | w[7]) == 0u);

    // ---- gather rows for this position across the batch ----
    int rows[BQ];
    if (is64) {
        const long long* x64 = (const long long*)xraw;
        #pragma unroll
        for (int b = 0; b < BQ; b++) rows[b] = (int)x64[(long long)b * S_LEN + s];
    } else {
        const int* x32 = (const int*)xraw;
        #pragma unroll
        for (int b = 0; b < BQ; b++) rows[b] = x32[b * S_LEN + s];
    }

    // ---- PE: 4 (sin,cos) pairs for this thread's 8 floats ----
    // pair i -> frequency index 4*lane+i; f = 2^(c_exp * idx)
    const float c_exp = -0.02595256324130752f;
    const float fs = (float)s;
    float p[8];
    #pragma unroll
    for (int i = 0; i < 4; i++) {
        float f = exp2f(c_exp * (float)(4 * lane + i));
        sincosf(fs * f, &p[2 * i], &p[2 * i + 1]);
    }

    // ---- gather + add + store, 256-bit accesses, default policy ----
    #pragma unroll
    for (int b = 0; b < BQ; b++) {
        float e[8];
        ldg_v8(emb + (long long)rows[b] * D_M + 8 * lane, e);
        float o[8];
        #pragma unroll
        for (int i = 0; i < 8; i++) o[i] = e[i] + p[i];
        stg_v8(out + ((long long)b * S_LEN + s) * D_M + 8 * lane, o);
    }
}

extern "C" void kernel_launch(void* const* d_in, const int* in_sizes, int n_in,
                              void* d_out, int out_size)
{
    const void*  x   = d_in[0];                 // [8, 4096] int64 (or int32)
    const float* emb = (const float*)d_in[1];   // [50257, 1024] fp32
    float*       out = (float*)d_out;           // [8, 4096, 1024] fp32

    sinemb_kernel<<<S_LEN / POS_PER_CTA, TPB>>>(x, emb, out);
}